// round 1
// baseline (speedup 1.0000x reference)
#include <cuda_runtime.h>

// BLIF: v[t] = exp(-exp(A_log[c])) * v[t-1] + x[t]
//       s[t] = (v[t] > 1)
//       out[0] = s[0]; out[t] = s[t] * (1 - s[t-1])   (pre-mask spikes)
//
// x: [T=256, B=8, C=128, H=14, W=14] f32, A_log: [128] f32, out: same as x.

#define T_LEN 256
#define PIX   200704          // B*C*H*W = 8*128*14*14
#define P4    (PIX / 4)       // 50176 float4 lanes; H*W=196 divisible by 4 -> one channel per lane
#define UNROLL 8

__global__ __launch_bounds__(256, 1)
void blif_scan_kernel(const float* __restrict__ x,
                      const float* __restrict__ A_log,
                      float* __restrict__ out)
{
    int p4 = blockIdx.x * blockDim.x + threadIdx.x;
    if (p4 >= P4) return;

    // channel of this 4-pixel lane: pixel = 4*p4, c = pixel/196 % 128 = p4/49 % 128
    int c = (p4 / 49) & 127;

    // decay in double to keep our rounding below the reference FFT's own error
    double a = exp((double)A_log[c]);
    float d = (float)exp(-a);

    const float4* __restrict__ xp = reinterpret_cast<const float4*>(x) + p4;
    float4*       __restrict__ op = reinterpret_cast<float4*>(out) + p4;

    float vx = 0.f, vy = 0.f, vz = 0.f, vw = 0.f;     // membrane state
    float px = 0.f, py = 0.f, pz = 0.f, pw = 0.f;     // previous pre-mask spike

    #pragma unroll 1
    for (int t0 = 0; t0 < T_LEN; t0 += UNROLL) {
        float4 xv[UNROLL];
        // batched independent loads -> MLP = UNROLL per thread
        #pragma unroll
        for (int j = 0; j < UNROLL; j++) {
            xv[j] = __ldcs(xp + (t0 + j) * P4);
        }
        #pragma unroll
        for (int j = 0; j < UNROLL; j++) {
            vx = fmaf(d, vx, xv[j].x);
            vy = fmaf(d, vy, xv[j].y);
            vz = fmaf(d, vz, xv[j].z);
            vw = fmaf(d, vw, xv[j].w);

            float sx = (vx > 1.0f) ? 1.0f : 0.0f;
            float sy = (vy > 1.0f) ? 1.0f : 0.0f;
            float sz = (vz > 1.0f) ? 1.0f : 0.0f;
            float sw = (vw > 1.0f) ? 1.0f : 0.0f;

            float4 o;
            o.x = sx * (1.0f - px);
            o.y = sy * (1.0f - py);
            o.z = sz * (1.0f - pz);
            o.w = sw * (1.0f - pw);

            px = sx; py = sy; pz = sz; pw = sw;

            __stcs(op + (t0 + j) * P4, o);
        }
    }
}

extern "C" void kernel_launch(void* const* d_in, const int* in_sizes, int n_in,
                              void* d_out, int out_size)
{
    const float* x     = (const float*)d_in[0];
    const float* A_log = (const float*)d_in[1];
    float*       out   = (float*)d_out;

    const int threads = 256;
    const int blocks  = (P4 + threads - 1) / threads;   // 196
    blif_scan_kernel<<<blocks, threads>>>(x, A_log, out);
}